// round 14
// baseline (speedup 1.0000x reference)
#include <cuda_runtime.h>
#include <cuda_bf16.h>
#include <stdint.h>

#define LN_EPS 1e-5f

namespace {
constexpr int NTHR1   = 512;   // pass1 threads
constexpr int NTHR3   = 512;   // pass3 threads
constexpr int P1CTAS  = 296;
constexpr int GRAM_E  = 1024;
constexpr int UE      = 48;
constexpr int PE      = GRAM_E + UE;   // 1072 per-CTA reduced partial entries
constexpr int MAXN    = 1 << 21;

// ---- pass1: CH=128, double-buffered fp32 X + single bf16 Z ----
constexpr int CH1     = 128;
constexpr int XP1     = 132;                       // fp32 words/row (132%32==4)
constexpr int ZP1     = 68;                        // u32 words/row  (68%32==4)
constexpr int XBUF_B  = 64 * XP1 * 4;              // 33792
constexpr int ZW_OFF  = 2 * XBUF_B;                // 67584
constexpr int AUX_OFF = ZW_OFF + 48 * ZP1 * 4;     // 80640
constexpr int MSV1_OFF = AUX_OFF + 3 * 128 * 8;    // 83712
constexpr int P1_SMEM = MSV1_OFF + 128 * 8;        // 84736 -> 2 CTAs/SM, 32 warps

// ---- pass3: CH=128, double-buffered, 512 threads x 2 CTAs ----
constexpr int CH      = 128;
constexpr int XP3     = 132;
constexpr int BUF_B   = 64 * XP3 * 4;              // 33792
constexpr int MSV_B   = CH * 8;
constexpr int P3_SMEM = 2 * BUF_B + 2 * MSV_B;     // 69632 -> 2 CTAs/SM
constexpr int P3CTAS  = 296;
}

// ---- scratch (allocation-free: __device__ globals) ----
__device__ float g_part[P1CTAS * PE];
__device__ float g_part2[8 * PE];
__device__ __align__(16) __nv_bfloat16 g_A[64 * 32];
__device__ float g_e[64];
__device__ float g_rs[64];
__device__ __align__(16) float2 g_msv[MAXN];

__device__ __forceinline__ void mma_m16n8k16(
    float& d0, float& d1, float& d2, float& d3,
    uint32_t a0, uint32_t a1, uint32_t a2, uint32_t a3,
    uint32_t b0, uint32_t b1)
{
    asm volatile(
        "mma.sync.aligned.m16n8k16.row.col.f32.bf16.bf16.f32 "
        "{%0,%1,%2,%3}, {%4,%5,%6,%7}, {%8,%9}, {%0,%1,%2,%3};\n"
        : "+f"(d0), "+f"(d1), "+f"(d2), "+f"(d3)
        : "r"(a0), "r"(a1), "r"(a2), "r"(a3), "r"(b0), "r"(b1));
}

__device__ __forceinline__ uint32_t pack_bf16(float lo, float hi) {
    __nv_bfloat162 b = __floats2bfloat162_rn(lo, hi);
    return *reinterpret_cast<uint32_t*>(&b);
}
__device__ __forceinline__ float bf_lo(uint32_t u) {
    __nv_bfloat162 b = *reinterpret_cast<__nv_bfloat162*>(&u);
    return __bfloat162float(b.x);
}
__device__ __forceinline__ float bf_hi(uint32_t u) {
    __nv_bfloat162 b = *reinterpret_cast<__nv_bfloat162*>(&u);
    return __bfloat162float(b.y);
}
__device__ __forceinline__ uint32_t smem_u32(const void* p) {
    return (uint32_t)__cvta_generic_to_shared(p);
}
__device__ __forceinline__ void cp16(uint32_t dst, const void* src) {
    asm volatile("cp.async.cg.shared.global [%0], [%1], 16;\n" :: "r"(dst), "l"(src));
}
__device__ __forceinline__ void cp_commit() {
    asm volatile("cp.async.commit_group;\n");
}
__device__ __forceinline__ void cp_wait1() {
    asm volatile("cp.async.wait_group 1;\n" ::: "memory");
}
__device__ __forceinline__ void cp_wait_all() {
    asm volatile("cp.async.wait_group 0;\n" ::: "memory");
}

// ============================================================================
// Pass 1 (persistent, 512 thr, double-buffered): stats kept in registers as
// bf16x2 -> normalize WITHOUT re-reading Xs; early prefetch after stats.
// Row sums + 32x32 Gram split over 4 k-quarters; in-CTA partial reduction.
// ============================================================================
__global__ __launch_bounds__(NTHR1, 2) void k_pass1(const float* __restrict__ x,
                                                    int N, int nchunks)
{
    extern __shared__ __align__(16) char smem[];
    uint32_t* Zw    = reinterpret_cast<uint32_t*>(smem + ZW_OFF);
    __nv_bfloat16* zh = reinterpret_cast<__nv_bfloat16*>(smem + ZW_OFF);
    float2*   aux   = reinterpret_cast<float2*>(smem + AUX_OFF);
    float2*   msv_s = reinterpret_cast<float2*>(smem + MSV1_OFF);
    const uint32_t base0 = smem_u32(smem);

    const int tid  = threadIdx.x;
    const int warp = tid >> 5;        // 0..15
    const int lane = tid & 31;
    const int g4   = lane >> 2;
    const int t4   = lane & 3;
    const int q    = warp & 3;        // gram quadrant
    const int kq   = warp >> 2;       // k-quarter 0..3
    const int m_off = (q >> 1) << 4;
    const int n_off = (q & 1) << 4;
    const int sc   = tid & 127;       // stats column
    const int sq   = tid >> 7;        // stats row-quarter 0..3

    const bool fastN = ((N & 3) == 0);

    float d[2][4];
#pragma unroll
    for (int j = 0; j < 2; j++)
#pragma unroll
        for (int i = 0; i < 4; i++) d[j][i] = 0.f;
    float ured[3] = {0.f, 0.f, 0.f};

#define P1_PREFETCH(IDX, BUFSEL)                                               \
    do {                                                                       \
        const int _i = (IDX);                                                  \
        if (_i < nchunks) {                                                    \
            const long _c0 = (long)_i * CH1;                                   \
            if (fastN && _c0 + CH1 <= (long)N) {                               \
                const uint32_t _xb = base0 + (BUFSEL) * XBUF_B;                \
                _Pragma("unroll")                                              \
                for (int _k = 0; _k < 4; _k++) {                               \
                    const int _ck = tid + 512 * _k;                            \
                    const int _row = _ck >> 5, _seg = _ck & 31;                \
                    cp16(_xb + (uint32_t)(_row * XP1 + _seg * 4) * 4u,         \
                         x + (size_t)_row * N + _c0 + _seg * 4);               \
                }                                                              \
            }                                                                  \
        }                                                                      \
        cp_commit();                                                           \
    } while (0)

    int idx = blockIdx.x;
    P1_PREFETCH(idx, 0);
    P1_PREFETCH(idx + gridDim.x, 1);

    int cur = 0;
    for (; idx < nchunks; idx += gridDim.x, cur ^= 1) {
        const long col0 = (long)idx * CH1;
        const bool fast = fastN && (col0 + CH1 <= (long)N);

        cp_wait1();
        float* Xs = reinterpret_cast<float*>(smem + cur * XBUF_B);

        if (!fast) {
#pragma unroll 1
            for (int i = tid; i < 64 * CH1; i += NTHR1) {
                const int r = i >> 7, cc = i & 127;
                const long c = col0 + cc;
                Xs[r * XP1 + cc] = (c < (long)N) ? __ldg(x + (size_t)r * N + c) : 0.f;
            }
            __syncthreads();
        }

        // ---- stats: column sc, row-quarter sq (16 rows); keep bf16x2 regs ----
        uint32_t vb[8];
        {
            float s1 = 0.f, s2 = 0.f;
            const float* px = &Xs[(sq * 16) * XP1 + sc];
#pragma unroll
            for (int p = 0; p < 8; p++) {
                const float va = px[(2 * p) * XP1];
                const float vc = px[(2 * p + 1) * XP1];
                s1 += va + vc;
                s2 = fmaf(va, va, s2);
                s2 = fmaf(vc, vc, s2);
                vb[p] = pack_bf16(va, vc);
            }
            if (sq) aux[(sq - 1) * 128 + sc] = make_float2(s1, s2);
            __syncthreads();          // Xs reads complete CTA-wide

            // refill this buffer as early as possible
            P1_PREFETCH(idx + 2 * gridDim.x, cur);

            if (!sq) {
#pragma unroll
                for (int a = 0; a < 3; a++) {
                    const float2 o = aux[a * 128 + sc];
                    s1 += o.x; s2 += o.y;
                }
                const float mu = s1 * (1.f / 64.f);
                const float rv = rsqrtf(s2 * (1.f / 64.f) - mu * mu + LN_EPS);
                msv_s[sc] = make_float2(mu, rv);
                if (col0 + sc < (long)N) g_msv[col0 + sc] = make_float2(mu, rv);
            }
        }
        __syncthreads();

        // ---- normalize own rows from registers (rows 0..47 only) ----
        if (sq < 3) {
            const float2 mv = msv_s[sc];
#pragma unroll
            for (int p = 0; p < 8; p++) {
                const int r = sq * 16 + 2 * p;
                const float za = (bf_lo(vb[p]) - mv.x) * mv.y;
                const float zc = (bf_hi(vb[p]) - mv.x) * mv.y;
                zh[r * (2 * ZP1) + sc]       = __float2bfloat16(za);
                zh[(r + 1) * (2 * ZP1) + sc] = __float2bfloat16(zc);
            }
        }
        __syncthreads();   // Zw ready

        // ---- row sums u (16 warps x 3 rows) ----
#pragma unroll
        for (int rr = 0; rr < 3; rr++) {
            const int row = warp + rr * 16;
            const uint32_t w1 = Zw[row * ZP1 + lane];
            const uint32_t w2 = Zw[row * ZP1 + lane + 32];
            float s = bf_lo(w1) + bf_hi(w1) + bf_lo(w2) + bf_hi(w2);
#pragma unroll
            for (int off = 16; off; off >>= 1)
                s += __shfl_xor_sync(0xffffffffu, s, off);
            ured[rr] += s;
        }

        // ---- Gram quadrant (m_off,n_off), k-quarter kq: 2 k-steps x 2 n8 ----
        const int ra = m_off + g4;
#pragma unroll
        for (int kk = 0; kk < 2; kk++) {
            const int kw = (kq * 2 + kk) * 8 + t4;
            uint32_t a0 = Zw[ra * ZP1 + kw];
            uint32_t a1 = Zw[(ra + 8) * ZP1 + kw];
            uint32_t a2 = Zw[ra * ZP1 + kw + 4];
            uint32_t a3 = Zw[(ra + 8) * ZP1 + kw + 4];
#pragma unroll
            for (int j = 0; j < 2; j++) {
                const int rb = 16 + n_off + 8 * j + g4;
                uint32_t b0 = Zw[rb * ZP1 + kw];
                uint32_t b1 = Zw[rb * ZP1 + kw + 4];
                mma_m16n8k16(d[j][0], d[j][1], d[j][2], d[j][3],
                             a0, a1, a2, a3, b0, b1);
            }
        }
        __syncthreads();   // Zw consumed before next normalize
    }
#undef P1_PREFETCH

    // ---- in-CTA reduction: drain async copies, reuse Xs as scratch ----
    cp_wait_all();
    __syncthreads();
    float* Fred = reinterpret_cast<float*>(smem);

    {
        const int row0 = m_off + g4;
#pragma unroll
        for (int j = 0; j < 2; j++) {
            const int colp = n_off + 8 * j + t4 * 2;
            float* fb = &Fred[kq * GRAM_E];
            fb[row0 * 32 + colp]           = d[j][0];
            fb[row0 * 32 + colp + 1]       = d[j][1];
            fb[(row0 + 8) * 32 + colp]     = d[j][2];
            fb[(row0 + 8) * 32 + colp + 1] = d[j][3];
        }
        if (lane == 0) {
#pragma unroll
            for (int rr = 0; rr < 3; rr++)
                Fred[4 * GRAM_E + warp + rr * 16] = ured[rr];
        }
    }
    __syncthreads();

    float* pp = g_part + (size_t)blockIdx.x * PE;
#pragma unroll 1
    for (int e = tid; e < PE; e += NTHR1) {
        if (e < GRAM_E) {
            pp[e] = Fred[e] + Fred[GRAM_E + e] + Fred[2 * GRAM_E + e]
                  + Fred[3 * GRAM_E + e];
        } else {
            pp[e] = Fred[4 * GRAM_E + (e - GRAM_E)];
        }
    }
}

// ============================================================================
// Reduce stage A: block (bx, s) sums CTA slice [37s, 37s+37).
// ============================================================================
__global__ void k_reduceA(int nb)
{
    const int e = blockIdx.x * 256 + threadIdx.x;
    if (e >= PE) return;
    const int s = blockIdx.y;
    const int c0 = s * 37;
    int c1 = c0 + 37; if (c1 > nb) c1 = nb;
    float acc = 0.f;
    for (int c = c0; c < c1; c++)
        acc += g_part[(size_t)c * PE + e];
    g_part2[s * PE + e] = acc;
}

// ============================================================================
// Pass 2 (1 block, 512 threads): final slice reduce + logits -> softmax ->
// A[64x32], e[64], rs[64]. Thread (c, s): c=tid>>3 row, s=tid&7 8-lane group.
// ============================================================================
__global__ __launch_bounds__(512) void k_pass2(const float* __restrict__ gamma,
                                               const float* __restrict__ beta,
                                               const float* __restrict__ cw,
                                               const float* __restrict__ cb,
                                               float Nf)
{
    __shared__ float Gs[GRAM_E];
    __shared__ float us[UE];
    __shared__ float gs[64], bs[64];
    __shared__ float cws[192], cbs[192];
    __shared__ float attn[64][65];

    const int tid = threadIdx.x;
    const int c   = tid >> 3;
    const int s   = tid & 7;

    // fused reduceB: sum the 8 slice partials
#pragma unroll 1
    for (int i = tid; i < PE; i += 512) {
        float v = 0.f;
#pragma unroll
        for (int sl = 0; sl < 8; sl++)
            v += g_part2[sl * PE + i];
        if (i < GRAM_E) Gs[i] = v;
        else            us[i - GRAM_E] = v;
    }
    if (tid < 64) { gs[tid] = gamma[tid]; bs[tid] = beta[tid]; }
    if (tid < 192) { cws[tid] = cw[tid]; cbs[tid] = cb[tid]; }
    __syncthreads();

    const float wq = cws[c], bq = cbs[c];
    const int   iq = c / 3;
    const float gi = gs[iq], bi = bs[iq], ui = us[iq];
    const float ti = gi * ui + Nf * bi;

    float L[8];
    float mx = -1e30f;
#pragma unroll
    for (int t = 0; t < 8; t++) {
        const int b2 = 8 * s + t;
        const int   ik = (64 + b2) / 3;
        const float wk = cws[64 + b2], bk = cbs[64 + b2];
        const float gj = gs[ik], bj = bs[ik], uj = us[ik];
        const float tj = gj * uj + Nf * bj;
        const float Gz = Gs[iq * 32 + (ik - 16)];
        const float S  = gi * gj * Gz + gi * bj * ui + bi * gj * uj + Nf * bi * bj;
        const float l  = 0.125f * (wq * wk * S + wq * bk * ti + bq * wk * tj + Nf * bq * bk);
        L[t] = l;
        mx = fmaxf(mx, l);
    }
#pragma unroll
    for (int off = 4; off; off >>= 1)
        mx = fmaxf(mx, __shfl_xor_sync(0xffffffffu, mx, off));

    float se = 0.f;
#pragma unroll
    for (int t = 0; t < 8; t++) {
        L[t] = expf(L[t] - mx);
        se += L[t];
    }
#pragma unroll
    for (int off = 4; off; off >>= 1)
        se += __shfl_xor_sync(0xffffffffu, se, off);
    const float inv = 1.f / se;

    float eacc = 0.f;
#pragma unroll
    for (int t = 0; t < 8; t++) {
        const float a = L[t] * inv;
        attn[c][8 * s + t] = a;
        eacc += a * cbs[128 + 8 * s + t];
    }
    __syncthreads();

    float rssum = 0.f;
#pragma unroll
    for (int jj = 0; jj < 4; jj++) {
        const int j = 32 + s * 4 + jj;
        float P = 0.f;
        const int b0 = 3 * j - 128;
#pragma unroll
        for (int dd = 0; dd < 3; dd++) {
            const int bb = b0 + dd;
            if (bb >= 0 && bb < 64) P += attn[c][bb] * cws[128 + bb];
        }
        const float Av = P * gs[j];
        const __nv_bfloat16 ab = __float2bfloat16(Av);
        g_A[c * 32 + (j - 32)] = ab;
        rssum += __bfloat162float(ab);
        eacc  += P * bs[j];
    }
#pragma unroll
    for (int off = 4; off; off >>= 1) {
        eacc  += __shfl_xor_sync(0xffffffffu, eacc, off);
        rssum += __shfl_xor_sync(0xffffffffu, rssum, off);
    }
    if (s == 0) {
        g_e[c]  = eacc;
        g_rs[c] = rssum;
    }
}

// ============================================================================
// Pass 3 (persistent, pipelined, dedup fragments): 512 thr x 2 CTAs/SM.
// warp = (m-half 0/1) x (n-slice of 16 cols, 8 slices).
// ============================================================================
__global__ __launch_bounds__(NTHR3, 2) void k_pass3(const float* __restrict__ x,
                                                    float* __restrict__ out,
                                                    int N, int nchunks)
{
    extern __shared__ __align__(16) char smem[];
    const uint32_t base0 = smem_u32(smem);

    const int tid  = threadIdx.x;
    const int warp = tid >> 5;      // 0..15
    const int lane = tid & 31;
    const int g4   = lane >> 2;
    const int t4   = lane & 3;
    const bool fastN = ((N & 3) == 0);

    const int mh = warp >> 3;            // m-half: tiles {0,1} or {2,3}
    const int ns = (warp & 7) * 16;      // n-slice base (16 cols = 2 n8)

    uint32_t Af[2][2][4];
    float ee[2][2], rr[2][2];
#pragma unroll
    for (int j = 0; j < 2; j++) {
        const int mt = 2 * mh + j;
        const int r0 = 16 * mt + g4, r1 = r0 + 8;
#pragma unroll
        for (int s = 0; s < 2; s++) {
            const int k0 = s * 16 + t4 * 2;
            Af[j][s][0] = *reinterpret_cast<const uint32_t*>(&g_A[r0 * 32 + k0]);
            Af[j][s][1] = *reinterpret_cast<const uint32_t*>(&g_A[r1 * 32 + k0]);
            Af[j][s][2] = *reinterpret_cast<const uint32_t*>(&g_A[r0 * 32 + k0 + 8]);
            Af[j][s][3] = *reinterpret_cast<const uint32_t*>(&g_A[r1 * 32 + k0 + 8]);
        }
        ee[j][0] = g_e[r0];  ee[j][1] = g_e[r1];
        rr[j][0] = g_rs[r0]; rr[j][1] = g_rs[r1];
    }

#define P3_PREFETCH(IDX, BUFSEL)                                               \
    do {                                                                       \
        const int _i = (IDX);                                                  \
        if (_i < nchunks) {                                                    \
            const long _c0 = (long)_i * CH;                                    \
            if (fastN && _c0 + CH <= (long)N) {                                \
                const uint32_t _xb = base0 + (BUFSEL) * BUF_B;                 \
                _Pragma("unroll")                                              \
                for (int _k = 0; _k < 4; _k++) {                               \
                    const int _ck = tid + 512 * _k;                            \
                    const int _row = _ck >> 5, _seg = _ck & 31;                \
                    cp16(_xb + (uint32_t)(_row * XP3 + _seg * 4) * 4u,         \
                         x + (size_t)_row * N + _c0 + _seg * 4);               \
                }                                                              \
                if (tid < 64)                                                  \
                    cp16(base0 + 2 * BUF_B + (BUFSEL) * MSV_B + tid * 16,      \
                         reinterpret_cast<const char*>(&g_msv[_c0]) + tid * 16);\
            }                                                                  \
        }                                                                      \
        cp_commit();                                                           \
    } while (0)

    int idx = blockIdx.x;
    P3_PREFETCH(idx, 0);
    P3_PREFETCH(idx + gridDim.x, 1);

    int cur = 0;
    for (; idx < nchunks; idx += gridDim.x, cur ^= 1) {
        const long col0 = (long)idx * CH;
        const bool fast = fastN && (col0 + CH <= (long)N);

        cp_wait1();
        float*  Xs    = reinterpret_cast<float*>(smem + cur * BUF_B);
        float2* msv_s = reinterpret_cast<float2*>(smem + 2 * BUF_B + cur * MSV_B);

        if (!fast) {
#pragma unroll 1
            for (int i = tid; i < 64 * CH; i += NTHR3) {
                const int r = i >> 7, cc = i & 127;
                const long c = col0 + cc;
                Xs[r * XP3 + cc] = (c < (long)N) ? __ldg(x + (size_t)r * N + c) : 0.f;
            }
            if (tid < CH) {
                const long c = col0 + tid;
                msv_s[tid] = (c < (long)N) ? g_msv[c] : make_float2(0.f, 1.f);
            }
        }
        __syncthreads();

        // ---- 2 n8-blocks per warp; B-frags shared across both m-tiles ----
#pragma unroll
        for (int nc = 0; nc < 2; nc++) {
            const int nb   = ns + nc * 8;
            const int nrow = nb + g4;
            const int lcol = nb + 2 * t4;
            const long gc  = col0 + lcol;

            const int kr = 32 + 2 * t4;
            uint32_t b00 = pack_bf16(Xs[kr * XP3 + nrow],        Xs[(kr + 1) * XP3 + nrow]);
            uint32_t b01 = pack_bf16(Xs[(kr + 8) * XP3 + nrow],  Xs[(kr + 9) * XP3 + nrow]);
            uint32_t b10 = pack_bf16(Xs[(kr + 16) * XP3 + nrow], Xs[(kr + 17) * XP3 + nrow]);
            uint32_t b11 = pack_bf16(Xs[(kr + 24) * XP3 + nrow], Xs[(kr + 25) * XP3 + nrow]);

            float acc[2][4];
#pragma unroll
            for (int j = 0; j < 2; j++) {
                acc[j][0] = acc[j][1] = acc[j][2] = acc[j][3] = 0.f;
                mma_m16n8k16(acc[j][0], acc[j][1], acc[j][2], acc[j][3],
                             Af[j][0][0], Af[j][0][1], Af[j][0][2], Af[j][0][3], b00, b01);
                mma_m16n8k16(acc[j][0], acc[j][1], acc[j][2], acc[j][3],
                             Af[j][1][0], Af[j][1][1], Af[j][1][2], Af[j][1][3], b10, b11);
            }

            const float2 m0 = msv_s[lcol], m1 = msv_s[lcol + 1];

#pragma unroll
            for (int j = 0; j < 2; j++) {
                const int mt = 2 * mh + j;
                const int r0 = 16 * mt + g4, r1 = r0 + 8;
                const float2 xv0 = *reinterpret_cast<const float2*>(&Xs[r0 * XP3 + lcol]);
                const float2 xv1 = *reinterpret_cast<const float2*>(&Xs[r1 * XP3 + lcol]);

                float2 o0, o1;
                o0.x = xv0.x + ee[j][0] + m0.y * (acc[j][0] - m0.x * rr[j][0]);
                o0.y = xv0.y + ee[j][0] + m1.y * (acc[j][1] - m1.x * rr[j][0]);
                o1.x = xv1.x + ee[j][1] + m0.y * (acc[j][2] - m0.x * rr[j][1]);
                o1.y = xv1.y + ee[j][1] + m1.y * (acc[j][3] - m1.x * rr[j][1]);

                if (gc + 1 < (long)N) {
                    __stcs(reinterpret_cast<float2*>(out + (size_t)r0 * N + gc), o0);
                    __stcs(reinterpret_cast<float2*>(out + (size_t)r1 * N + gc), o1);
                } else if (gc < (long)N) {
                    out[(size_t)r0 * N + gc] = o0.x;
                    out[(size_t)r1 * N + gc] = o1.x;
                }
            }
        }
        __syncthreads();

        P3_PREFETCH(idx + 2 * gridDim.x, cur);
    }
#undef P3_PREFETCH
}

// ============================================================================
extern "C" void kernel_launch(void* const* d_in, const int* in_sizes, int n_in,
                              void* d_out, int out_size)
{
    const float* x     = (const float*)d_in[0];
    const float* gamma = (const float*)d_in[1];
    const float* beta  = (const float*)d_in[2];
    const float* cw    = (const float*)d_in[3];
    const float* cb    = (const float*)d_in[4];
    float* out = (float*)d_out;

    const int N = in_sizes[0] / 64;
    const int nchunks1 = (N + CH1 - 1) / CH1;
    const int nb1 = nchunks1 < P1CTAS ? nchunks1 : P1CTAS;
    const int nchunks3 = (N + CH - 1) / CH;
    const int nb3 = nchunks3 < P3CTAS ? nchunks3 : P3CTAS;

    cudaFuncSetAttribute(k_pass1, cudaFuncAttributeMaxDynamicSharedMemorySize, P1_SMEM);
    cudaFuncSetAttribute(k_pass3, cudaFuncAttributeMaxDynamicSharedMemorySize, P3_SMEM);

    k_pass1<<<nb1, NTHR1, P1_SMEM>>>(x, N, nchunks1);
    k_reduceA<<<dim3((PE + 255) / 256, 8), 256>>>(nb1);
    k_pass2<<<1, 512>>>(gamma, beta, cw, cb, (float)N);
    k_pass3<<<nb3, NTHR3, P3_SMEM>>>(x, out, N, nchunks3);
}

// round 15
// speedup vs baseline: 1.0078x; 1.0078x over previous
#include <cuda_runtime.h>
#include <cuda_bf16.h>
#include <stdint.h>

#define LN_EPS 1e-5f

namespace {
constexpr int NTHR1   = 512;   // pass1 threads
constexpr int NTHR3   = 512;   // pass3 threads
constexpr int P1CTAS  = 296;
constexpr int GRAM_E  = 1024;
constexpr int UE      = 48;
constexpr int PE      = GRAM_E + UE;   // 1072 per-CTA reduced partial entries
constexpr int MAXN    = 1 << 21;

// ---- pass1: CH=128, double-buffered fp32 X + single bf16 Z ----
constexpr int CH1     = 128;
constexpr int XP1     = 132;                       // fp32 words/row (132%32==4)
constexpr int ZP1     = 68;                        // u32 words/row  (68%32==4)
constexpr int XBUF_B  = 64 * XP1 * 4;              // 33792
constexpr int ZW_OFF  = 2 * XBUF_B;                // 67584
constexpr int AUX_OFF = ZW_OFF + 48 * ZP1 * 4;     // 80640
constexpr int MSV1_OFF = AUX_OFF + 3 * 128 * 8;    // 83712
constexpr int P1_SMEM = MSV1_OFF + 128 * 8;        // 84736 -> 2 CTAs/SM, 32 warps

// ---- pass3: CH=128, double-buffered, 512 threads x 2 CTAs ----
constexpr int CH      = 128;
constexpr int XP3     = 132;
constexpr int BUF_B   = 64 * XP3 * 4;              // 33792
constexpr int MSV_B   = CH * 8;
constexpr int P3_SMEM = 2 * BUF_B + 2 * MSV_B;     // 69632 -> 2 CTAs/SM
constexpr int P3CTAS  = 296;
}

// ---- scratch (allocation-free: __device__ globals) ----
__device__ float g_part[P1CTAS * PE];
__device__ float g_part2[8 * PE];
__device__ __align__(16) __nv_bfloat16 g_A[64 * 32];
__device__ float g_e[64];
__device__ float g_rs[64];
__device__ __align__(16) float2 g_msv[MAXN];

__device__ __forceinline__ void mma_m16n8k16(
    float& d0, float& d1, float& d2, float& d3,
    uint32_t a0, uint32_t a1, uint32_t a2, uint32_t a3,
    uint32_t b0, uint32_t b1)
{
    asm volatile(
        "mma.sync.aligned.m16n8k16.row.col.f32.bf16.bf16.f32 "
        "{%0,%1,%2,%3}, {%4,%5,%6,%7}, {%8,%9}, {%0,%1,%2,%3};\n"
        : "+f"(d0), "+f"(d1), "+f"(d2), "+f"(d3)
        : "r"(a0), "r"(a1), "r"(a2), "r"(a3), "r"(b0), "r"(b1));
}

__device__ __forceinline__ uint32_t pack_bf16(float lo, float hi) {
    __nv_bfloat162 b = __floats2bfloat162_rn(lo, hi);
    return *reinterpret_cast<uint32_t*>(&b);
}
__device__ __forceinline__ float bf_lo(uint32_t u) {
    __nv_bfloat162 b = *reinterpret_cast<__nv_bfloat162*>(&u);
    return __bfloat162float(b.x);
}
__device__ __forceinline__ float bf_hi(uint32_t u) {
    __nv_bfloat162 b = *reinterpret_cast<__nv_bfloat162*>(&u);
    return __bfloat162float(b.y);
}
__device__ __forceinline__ uint32_t smem_u32(const void* p) {
    return (uint32_t)__cvta_generic_to_shared(p);
}
__device__ __forceinline__ void cp16(uint32_t dst, const void* src) {
    asm volatile("cp.async.cg.shared.global [%0], [%1], 16;\n" :: "r"(dst), "l"(src));
}
__device__ __forceinline__ void cp_commit() {
    asm volatile("cp.async.commit_group;\n");
}
__device__ __forceinline__ void cp_wait1() {
    asm volatile("cp.async.wait_group 1;\n" ::: "memory");
}
__device__ __forceinline__ void cp_wait_all() {
    asm volatile("cp.async.wait_group 0;\n" ::: "memory");
}

// ============================================================================
// Pass 1 (persistent, 512 thr, double-buffered) — R13 version: stats via smem
// aux, normalize re-reads Xs as float2, packed u32 Zw stores.
// ============================================================================
__global__ __launch_bounds__(NTHR1, 2) void k_pass1(const float* __restrict__ x,
                                                    int N, int nchunks)
{
    extern __shared__ __align__(16) char smem[];
    uint32_t* Zw    = reinterpret_cast<uint32_t*>(smem + ZW_OFF);
    float2*   aux   = reinterpret_cast<float2*>(smem + AUX_OFF);
    float2*   msv_s = reinterpret_cast<float2*>(smem + MSV1_OFF);
    const uint32_t base0 = smem_u32(smem);

    const int tid  = threadIdx.x;
    const int warp = tid >> 5;        // 0..15
    const int lane = tid & 31;
    const int g4   = lane >> 2;
    const int t4   = lane & 3;
    const int q    = warp & 3;        // gram quadrant
    const int kq   = warp >> 2;       // k-quarter 0..3
    const int m_off = (q >> 1) << 4;
    const int n_off = (q & 1) << 4;
    const int sc   = tid & 127;       // stats column
    const int sq   = tid >> 7;        // stats row-quarter 0..3
    const int np   = tid & 63;        // normalize column-pair
    const int ng   = tid >> 6;        // normalize row-group 0..7

    const bool fastN = ((N & 3) == 0);

    float d[2][4];
#pragma unroll
    for (int j = 0; j < 2; j++)
#pragma unroll
        for (int i = 0; i < 4; i++) d[j][i] = 0.f;
    float ured[3] = {0.f, 0.f, 0.f};

#define P1_PREFETCH(IDX, BUFSEL)                                               \
    do {                                                                       \
        const int _i = (IDX);                                                  \
        if (_i < nchunks) {                                                    \
            const long _c0 = (long)_i * CH1;                                   \
            if (fastN && _c0 + CH1 <= (long)N) {                               \
                const uint32_t _xb = base0 + (BUFSEL) * XBUF_B;                \
                _Pragma("unroll")                                              \
                for (int _k = 0; _k < 4; _k++) {                               \
                    const int _ck = tid + 512 * _k;                            \
                    const int _row = _ck >> 5, _seg = _ck & 31;                \
                    cp16(_xb + (uint32_t)(_row * XP1 + _seg * 4) * 4u,         \
                         x + (size_t)_row * N + _c0 + _seg * 4);               \
                }                                                              \
            }                                                                  \
        }                                                                      \
        cp_commit();                                                           \
    } while (0)

    int idx = blockIdx.x;
    P1_PREFETCH(idx, 0);
    P1_PREFETCH(idx + gridDim.x, 1);

    int cur = 0;
    for (; idx < nchunks; idx += gridDim.x, cur ^= 1) {
        const long col0 = (long)idx * CH1;
        const bool fast = fastN && (col0 + CH1 <= (long)N);

        cp_wait1();
        float* Xs = reinterpret_cast<float*>(smem + cur * XBUF_B);

        if (!fast) {
#pragma unroll 1
            for (int i = tid; i < 64 * CH1; i += NTHR1) {
                const int r = i >> 7, cc = i & 127;
                const long c = col0 + cc;
                Xs[r * XP1 + cc] = (c < (long)N) ? __ldg(x + (size_t)r * N + c) : 0.f;
            }
        }
        __syncthreads();

        // ---- stats: column sc, row-quarter sq (16 rows each) ----
        {
            float s1 = 0.f, s2 = 0.f;
            const float* px = &Xs[(sq * 16) * XP1 + sc];
#pragma unroll
            for (int r = 0; r < 16; r++) {
                const float v = px[r * XP1];
                s1 += v;
                s2 = fmaf(v, v, s2);
            }
            if (sq) aux[(sq - 1) * 128 + sc] = make_float2(s1, s2);
            __syncthreads();
            if (!sq) {
#pragma unroll
                for (int a = 0; a < 3; a++) {
                    const float2 o = aux[a * 128 + sc];
                    s1 += o.x; s2 += o.y;
                }
                const float mu = s1 * (1.f / 64.f);
                const float rv = rsqrtf(s2 * (1.f / 64.f) - mu * mu + LN_EPS);
                msv_s[sc] = make_float2(mu, rv);
                if (col0 + sc < (long)N) g_msv[col0 + sc] = make_float2(mu, rv);
            }
        }
        __syncthreads();

        // ---- normalize rows 0..47 (colpair np, row-group ng: 6 rows) ----
        {
            const float2 mv0 = msv_s[2 * np];
            const float2 mv1 = msv_s[2 * np + 1];
#pragma unroll
            for (int j = 0; j < 6; j++) {
                const int r = ng * 6 + j;
                const float2 v = *reinterpret_cast<const float2*>(&Xs[r * XP1 + 2 * np]);
                Zw[r * ZP1 + np] =
                    pack_bf16((v.x - mv0.x) * mv0.y, (v.y - mv1.x) * mv1.y);
            }
        }
        __syncthreads();   // Zw ready; Xs[cur] free

        // ---- refill this buffer (overlaps rowsum + Gram + next wait) ----
        P1_PREFETCH(idx + 2 * gridDim.x, cur);

        // ---- row sums u (16 warps x 3 rows) ----
#pragma unroll
        for (int rr = 0; rr < 3; rr++) {
            const int row = warp + rr * 16;
            const uint32_t w1 = Zw[row * ZP1 + lane];
            const uint32_t w2 = Zw[row * ZP1 + lane + 32];
            float s = bf_lo(w1) + bf_hi(w1) + bf_lo(w2) + bf_hi(w2);
#pragma unroll
            for (int off = 16; off; off >>= 1)
                s += __shfl_xor_sync(0xffffffffu, s, off);
            ured[rr] += s;
        }

        // ---- Gram quadrant (m_off,n_off), k-quarter kq: 2 k-steps x 2 n8 ----
        const int ra = m_off + g4;
#pragma unroll
        for (int kk = 0; kk < 2; kk++) {
            const int kw = (kq * 2 + kk) * 8 + t4;
            uint32_t a0 = Zw[ra * ZP1 + kw];
            uint32_t a1 = Zw[(ra + 8) * ZP1 + kw];
            uint32_t a2 = Zw[ra * ZP1 + kw + 4];
            uint32_t a3 = Zw[(ra + 8) * ZP1 + kw + 4];
#pragma unroll
            for (int j = 0; j < 2; j++) {
                const int rb = 16 + n_off + 8 * j + g4;
                uint32_t b0 = Zw[rb * ZP1 + kw];
                uint32_t b1 = Zw[rb * ZP1 + kw + 4];
                mma_m16n8k16(d[j][0], d[j][1], d[j][2], d[j][3],
                             a0, a1, a2, a3, b0, b1);
            }
        }
        __syncthreads();   // Zw consumed before next normalize
    }
#undef P1_PREFETCH

    // ---- in-CTA reduction: drain async copies, reuse Xs as scratch ----
    cp_wait_all();
    __syncthreads();
    float* Fred = reinterpret_cast<float*>(smem);

    {
        const int row0 = m_off + g4;
#pragma unroll
        for (int j = 0; j < 2; j++) {
            const int colp = n_off + 8 * j + t4 * 2;
            float* fb = &Fred[kq * GRAM_E];
            fb[row0 * 32 + colp]           = d[j][0];
            fb[row0 * 32 + colp + 1]       = d[j][1];
            fb[(row0 + 8) * 32 + colp]     = d[j][2];
            fb[(row0 + 8) * 32 + colp + 1] = d[j][3];
        }
        if (lane == 0) {
#pragma unroll
            for (int rr = 0; rr < 3; rr++)
                Fred[4 * GRAM_E + warp + rr * 16] = ured[rr];
        }
    }
    __syncthreads();

    float* pp = g_part + (size_t)blockIdx.x * PE;
#pragma unroll 1
    for (int e = tid; e < PE; e += NTHR1) {
        if (e < GRAM_E) {
            pp[e] = Fred[e] + Fred[GRAM_E + e] + Fred[2 * GRAM_E + e]
                  + Fred[3 * GRAM_E + e];
        } else {
            pp[e] = Fred[4 * GRAM_E + (e - GRAM_E)];
        }
    }
}

// ============================================================================
// Reduce stage A: block (bx, s) sums CTA slice [37s, 37s+37).
// ============================================================================
__global__ void k_reduceA(int nb)
{
    const int e = blockIdx.x * 256 + threadIdx.x;
    if (e >= PE) return;
    const int s = blockIdx.y;
    const int c0 = s * 37;
    int c1 = c0 + 37; if (c1 > nb) c1 = nb;
    float acc = 0.f;
    for (int c = c0; c < c1; c++)
        acc += g_part[(size_t)c * PE + e];
    g_part2[s * PE + e] = acc;
}

// ============================================================================
// Pass 2 (1 block, 512 threads): final slice reduce + logits -> softmax ->
// A[64x32], e[64], rs[64]. Thread (c, s): c=tid>>3 row, s=tid&7 8-lane group.
// ============================================================================
__global__ __launch_bounds__(512) void k_pass2(const float* __restrict__ gamma,
                                               const float* __restrict__ beta,
                                               const float* __restrict__ cw,
                                               const float* __restrict__ cb,
                                               float Nf)
{
    __shared__ float Gs[GRAM_E];
    __shared__ float us[UE];
    __shared__ float gs[64], bs[64];
    __shared__ float cws[192], cbs[192];
    __shared__ float attn[64][65];

    const int tid = threadIdx.x;
    const int c   = tid >> 3;
    const int s   = tid & 7;

    // fused reduceB: sum the 8 slice partials
#pragma unroll 1
    for (int i = tid; i < PE; i += 512) {
        float v = 0.f;
#pragma unroll
        for (int sl = 0; sl < 8; sl++)
            v += g_part2[sl * PE + i];
        if (i < GRAM_E) Gs[i] = v;
        else            us[i - GRAM_E] = v;
    }
    if (tid < 64) { gs[tid] = gamma[tid]; bs[tid] = beta[tid]; }
    if (tid < 192) { cws[tid] = cw[tid]; cbs[tid] = cb[tid]; }
    __syncthreads();

    const float wq = cws[c], bq = cbs[c];
    const int   iq = c / 3;
    const float gi = gs[iq], bi = bs[iq], ui = us[iq];
    const float ti = gi * ui + Nf * bi;

    float L[8];
    float mx = -1e30f;
#pragma unroll
    for (int t = 0; t < 8; t++) {
        const int b2 = 8 * s + t;
        const int   ik = (64 + b2) / 3;
        const float wk = cws[64 + b2], bk = cbs[64 + b2];
        const float gj = gs[ik], bj = bs[ik], uj = us[ik];
        const float tj = gj * uj + Nf * bj;
        const float Gz = Gs[iq * 32 + (ik - 16)];
        const float S  = gi * gj * Gz + gi * bj * ui + bi * gj * uj + Nf * bi * bj;
        const float l  = 0.125f * (wq * wk * S + wq * bk * ti + bq * wk * tj + Nf * bq * bk);
        L[t] = l;
        mx = fmaxf(mx, l);
    }
#pragma unroll
    for (int off = 4; off; off >>= 1)
        mx = fmaxf(mx, __shfl_xor_sync(0xffffffffu, mx, off));

    float se = 0.f;
#pragma unroll
    for (int t = 0; t < 8; t++) {
        L[t] = expf(L[t] - mx);
        se += L[t];
    }
#pragma unroll
    for (int off = 4; off; off >>= 1)
        se += __shfl_xor_sync(0xffffffffu, se, off);
    const float inv = 1.f / se;

    float eacc = 0.f;
#pragma unroll
    for (int t = 0; t < 8; t++) {
        const float a = L[t] * inv;
        attn[c][8 * s + t] = a;
        eacc += a * cbs[128 + 8 * s + t];
    }
    __syncthreads();

    float rssum = 0.f;
#pragma unroll
    for (int jj = 0; jj < 4; jj++) {
        const int j = 32 + s * 4 + jj;
        float P = 0.f;
        const int b0 = 3 * j - 128;
#pragma unroll
        for (int dd = 0; dd < 3; dd++) {
            const int bb = b0 + dd;
            if (bb >= 0 && bb < 64) P += attn[c][bb] * cws[128 + bb];
        }
        const float Av = P * gs[j];
        const __nv_bfloat16 ab = __float2bfloat16(Av);
        g_A[c * 32 + (j - 32)] = ab;
        rssum += __bfloat162float(ab);
        eacc  += P * bs[j];
    }
#pragma unroll
    for (int off = 4; off; off >>= 1) {
        eacc  += __shfl_xor_sync(0xffffffffu, eacc, off);
        rssum += __shfl_xor_sync(0xffffffffu, rssum, off);
    }
    if (s == 0) {
        g_e[c]  = eacc;
        g_rs[c] = rssum;
    }
}

// ============================================================================
// Pass 3 (persistent, pipelined, dedup fragments): 512 thr x 2 CTAs/SM.
// warp = (m-half 0/1) x (n-slice of 16 cols, 8 slices).
// ============================================================================
__global__ __launch_bounds__(NTHR3, 2) void k_pass3(const float* __restrict__ x,
                                                    float* __restrict__ out,
                                                    int N, int nchunks)
{
    extern __shared__ __align__(16) char smem[];
    const uint32_t base0 = smem_u32(smem);

    const int tid  = threadIdx.x;
    const int warp = tid >> 5;      // 0..15
    const int lane = tid & 31;
    const int g4   = lane >> 2;
    const int t4   = lane & 3;
    const bool fastN = ((N & 3) == 0);

    const int mh = warp >> 3;            // m-half: tiles {0,1} or {2,3}
    const int ns = (warp & 7) * 16;      // n-slice base (16 cols = 2 n8)

    uint32_t Af[2][2][4];
    float ee[2][2], rr[2][2];
#pragma unroll
    for (int j = 0; j < 2; j++) {
        const int mt = 2 * mh + j;
        const int r0 = 16 * mt + g4, r1 = r0 + 8;
#pragma unroll
        for (int s = 0; s < 2; s++) {
            const int k0 = s * 16 + t4 * 2;
            Af[j][s][0] = *reinterpret_cast<const uint32_t*>(&g_A[r0 * 32 + k0]);
            Af[j][s][1] = *reinterpret_cast<const uint32_t*>(&g_A[r1 * 32 + k0]);
            Af[j][s][2] = *reinterpret_cast<const uint32_t*>(&g_A[r0 * 32 + k0 + 8]);
            Af[j][s][3] = *reinterpret_cast<const uint32_t*>(&g_A[r1 * 32 + k0 + 8]);
        }
        ee[j][0] = g_e[r0];  ee[j][1] = g_e[r1];
        rr[j][0] = g_rs[r0]; rr[j][1] = g_rs[r1];
    }

#define P3_PREFETCH(IDX, BUFSEL)                                               \
    do {                                                                       \
        const int _i = (IDX);                                                  \
        if (_i < nchunks) {                                                    \
            const long _c0 = (long)_i * CH;                                    \
            if (fastN && _c0 + CH <= (long)N) {                                \
                const uint32_t _xb = base0 + (BUFSEL) * BUF_B;                 \
                _Pragma("unroll")                                              \
                for (int _k = 0; _k < 4; _k++) {                               \
                    const int _ck = tid + 512 * _k;                            \
                    const int _row = _ck >> 5, _seg = _ck & 31;                \
                    cp16(_xb + (uint32_t)(_row * XP3 + _seg * 4) * 4u,         \
                         x + (size_t)_row * N + _c0 + _seg * 4);               \
                }                                                              \
                if (tid < 64)                                                  \
                    cp16(base0 + 2 * BUF_B + (BUFSEL) * MSV_B + tid * 16,      \
                         reinterpret_cast<const char*>(&g_msv[_c0]) + tid * 16);\
            }                                                                  \
        }                                                                      \
        cp_commit();                                                           \
    } while (0)

    int idx = blockIdx.x;
    P3_PREFETCH(idx, 0);
    P3_PREFETCH(idx + gridDim.x, 1);

    int cur = 0;
    for (; idx < nchunks; idx += gridDim.x, cur ^= 1) {
        const long col0 = (long)idx * CH;
        const bool fast = fastN && (col0 + CH <= (long)N);

        cp_wait1();
        float*  Xs    = reinterpret_cast<float*>(smem + cur * BUF_B);
        float2* msv_s = reinterpret_cast<float2*>(smem + 2 * BUF_B + cur * MSV_B);

        if (!fast) {
#pragma unroll 1
            for (int i = tid; i < 64 * CH; i += NTHR3) {
                const int r = i >> 7, cc = i & 127;
                const long c = col0 + cc;
                Xs[r * XP3 + cc] = (c < (long)N) ? __ldg(x + (size_t)r * N + c) : 0.f;
            }
            if (tid < CH) {
                const long c = col0 + tid;
                msv_s[tid] = (c < (long)N) ? g_msv[c] : make_float2(0.f, 1.f);
            }
        }
        __syncthreads();

        // ---- 2 n8-blocks per warp; B-frags shared across both m-tiles ----
#pragma unroll
        for (int nc = 0; nc < 2; nc++) {
            const int nb   = ns + nc * 8;
            const int nrow = nb + g4;
            const int lcol = nb + 2 * t4;
            const long gc  = col0 + lcol;

            const int kr = 32 + 2 * t4;
            uint32_t b00 = pack_bf16(Xs[kr * XP3 + nrow],        Xs[(kr + 1) * XP3 + nrow]);
            uint32_t b01 = pack_bf16(Xs[(kr + 8) * XP3 + nrow],  Xs[(kr + 9) * XP3 + nrow]);
            uint32_t b10 = pack_bf16(Xs[(kr + 16) * XP3 + nrow], Xs[(kr + 17) * XP3 + nrow]);
            uint32_t b11 = pack_bf16(Xs[(kr + 24) * XP3 + nrow], Xs[(kr + 25) * XP3 + nrow]);

            float acc[2][4];
#pragma unroll
            for (int j = 0; j < 2; j++) {
                acc[j][0] = acc[j][1] = acc[j][2] = acc[j][3] = 0.f;
                mma_m16n8k16(acc[j][0], acc[j][1], acc[j][2], acc[j][3],
                             Af[j][0][0], Af[j][0][1], Af[j][0][2], Af[j][0][3], b00, b01);
                mma_m16n8k16(acc[j][0], acc[j][1], acc[j][2], acc[j][3],
                             Af[j][1][0], Af[j][1][1], Af[j][1][2], Af[j][1][3], b10, b11);
            }

            const float2 m0 = msv_s[lcol], m1 = msv_s[lcol + 1];

#pragma unroll
            for (int j = 0; j < 2; j++) {
                const int mt = 2 * mh + j;
                const int r0 = 16 * mt + g4, r1 = r0 + 8;
                const float2 xv0 = *reinterpret_cast<const float2*>(&Xs[r0 * XP3 + lcol]);
                const float2 xv1 = *reinterpret_cast<const float2*>(&Xs[r1 * XP3 + lcol]);

                float2 o0, o1;
                o0.x = xv0.x + ee[j][0] + m0.y * (acc[j][0] - m0.x * rr[j][0]);
                o0.y = xv0.y + ee[j][0] + m1.y * (acc[j][1] - m1.x * rr[j][0]);
                o1.x = xv1.x + ee[j][1] + m0.y * (acc[j][2] - m0.x * rr[j][1]);
                o1.y = xv1.y + ee[j][1] + m1.y * (acc[j][3] - m1.x * rr[j][1]);

                if (gc + 1 < (long)N) {
                    __stcs(reinterpret_cast<float2*>(out + (size_t)r0 * N + gc), o0);
                    __stcs(reinterpret_cast<float2*>(out + (size_t)r1 * N + gc), o1);
                } else if (gc < (long)N) {
                    out[(size_t)r0 * N + gc] = o0.x;
                    out[(size_t)r1 * N + gc] = o1.x;
                }
            }
        }
        __syncthreads();

        P3_PREFETCH(idx + 2 * gridDim.x, cur);
    }
#undef P3_PREFETCH
}

// ============================================================================
extern "C" void kernel_launch(void* const* d_in, const int* in_sizes, int n_in,
                              void* d_out, int out_size)
{
    const float* x     = (const float*)d_in[0];
    const float* gamma = (const float*)d_in[1];
    const float* beta  = (const float*)d_in[2];
    const float* cw    = (const float*)d_in[3];
    const float* cb    = (const float*)d_in[4];
    float* out = (float*)d_out;

    const int N = in_sizes[0] / 64;
    const int nchunks1 = (N + CH1 - 1) / CH1;
    const int nb1 = nchunks1 < P1CTAS ? nchunks1 : P1CTAS;
    const int nchunks3 = (N + CH - 1) / CH;
    const int nb3 = nchunks3 < P3CTAS ? nchunks3 : P3CTAS;

    cudaFuncSetAttribute(k_pass1, cudaFuncAttributeMaxDynamicSharedMemorySize, P1_SMEM);
    cudaFuncSetAttribute(k_pass3, cudaFuncAttributeMaxDynamicSharedMemorySize, P3_SMEM);

    k_pass1<<<nb1, NTHR1, P1_SMEM>>>(x, N, nchunks1);
    k_reduceA<<<dim3((PE + 255) / 256, 8), 256>>>(nb1);
    k_pass2<<<1, 512>>>(gamma, beta, cw, cb, (float)N);
    k_pass3<<<nb3, NTHR3, P3_SMEM>>>(x, out, N, nchunks3);
}